// round 1
// baseline (speedup 1.0000x reference)
#include <cuda_runtime.h>

#define E_DIM 1024
#define D_DIM 64
#define B_DIM 4
#define T_DIM 4096
#define M_ROWS (B_DIM * T_DIM)   // 16384

// Scratch for Q, K, V: [B*T, D] fp32 each (4 MB each). Device globals (no allocs).
__device__ float g_q[M_ROWS * D_DIM];
__device__ float g_k[M_ROWS * D_DIM];
__device__ float g_v[M_ROWS * D_DIM];

// ---------------------------------------------------------------------------
// Kernel 1: QKV projection.  C[m, d] = sum_e x[m, e] * W[e, d]
// M=16384, N=64, K=1024. Block tile 128x64, BK=32, 256 threads, 8x4 per thread.
// blockIdx.y selects which of (Wq->g_q, Wk->g_k, Wv->g_v).
// ---------------------------------------------------------------------------
__global__ __launch_bounds__(256)
void qkv_kernel(const float* __restrict__ x,
                const float* __restrict__ Wq,
                const float* __restrict__ Wk,
                const float* __restrict__ Wv)
{
    constexpr int BM = 128, BK = 32, BN = 64;
    constexpr int AS = BK + 1;           // padded row stride for A tile
    __shared__ float As[BM * AS];        // [m][k], stride 33
    __shared__ float Bs[BK * BN];        // [k][n], stride 64

    const int tid = threadIdx.x;
    const int ty  = tid >> 4;            // 0..15 -> rows ty*8 .. ty*8+7
    const int tx  = tid & 15;            // 0..15 -> cols tx*4 .. tx*4+3
    const int m0  = blockIdx.x * BM;

    const float* W;
    float* C;
    if (blockIdx.y == 0)      { W = Wq; C = g_q; }
    else if (blockIdx.y == 1) { W = Wk; C = g_k; }
    else                      { W = Wv; C = g_v; }

    float c[8][4];
    #pragma unroll
    for (int i = 0; i < 8; i++)
        #pragma unroll
        for (int j = 0; j < 4; j++) c[i][j] = 0.f;

    for (int k0 = 0; k0 < E_DIM; k0 += BK) {
        // Load A tile 128x32 (4 float4 per thread)
        #pragma unroll
        for (int i = 0; i < 4; i++) {
            int f   = tid + 256 * i;
            int row = f >> 3;            // 0..127
            int kc  = (f & 7) << 2;      // 0..28
            float4 v = *reinterpret_cast<const float4*>(
                &x[(size_t)(m0 + row) * E_DIM + k0 + kc]);
            As[row * AS + kc + 0] = v.x;
            As[row * AS + kc + 1] = v.y;
            As[row * AS + kc + 2] = v.z;
            As[row * AS + kc + 3] = v.w;
        }
        // Load B tile 32x64 (2 float4 per thread)
        #pragma unroll
        for (int i = 0; i < 2; i++) {
            int f   = tid + 256 * i;
            int row = f >> 4;            // 0..31
            int c4  = (f & 15) << 2;     // 0..60
            *reinterpret_cast<float4*>(&Bs[row * BN + c4]) =
                *reinterpret_cast<const float4*>(&W[(size_t)(k0 + row) * BN + c4]);
        }
        __syncthreads();

        #pragma unroll
        for (int k = 0; k < BK; k++) {
            float a[8];
            #pragma unroll
            for (int i = 0; i < 8; i++) a[i] = As[(ty * 8 + i) * AS + k];
            float4 bv = *reinterpret_cast<const float4*>(&Bs[k * BN + tx * 4]);
            float b[4] = {bv.x, bv.y, bv.z, bv.w};
            #pragma unroll
            for (int i = 0; i < 8; i++)
                #pragma unroll
                for (int j = 0; j < 4; j++)
                    c[i][j] = fmaf(a[i], b[j], c[i][j]);
        }
        __syncthreads();
    }

    #pragma unroll
    for (int i = 0; i < 8; i++) {
        float4 v = make_float4(c[i][0], c[i][1], c[i][2], c[i][3]);
        *reinterpret_cast<float4*>(&C[(size_t)(m0 + ty * 8 + i) * D_DIM + tx * 4]) = v;
    }
}

// ---------------------------------------------------------------------------
// Kernel 2: fused flash attention (unscaled softmax; * 1/sqrt(D) at the end).
// Per block: one (batch b, 64-row q-tile). Loops over 64-row K/V tiles.
// 128 threads: ty = tid/8 (rows ty*4..+3), tx = tid%8 (cols tx*8..+7).
// Q,K in smem transposed [d][m] (stride 68 -> f4-aligned, conflict-free).
// P written transposed [n][m] (stride 68) for the P@V GEMM. V natural [n][d].
// ---------------------------------------------------------------------------
__global__ __launch_bounds__(128)
void attn_kernel(float* __restrict__ out)
{
    constexpr int BM = 64, BN = 64, DD = 64;
    constexpr int SQ = 68;  // padded m-stride for transposed tiles

    extern __shared__ float sm[];
    float* Qs = sm;                 // [DD][SQ]  : Qs[d*SQ + m]
    float* Ks = Qs + DD * SQ;       // [DD][SQ]  : Ks[d*SQ + n]
    float* Ps = Ks + DD * SQ;       // [BN][SQ]  : Ps[n*SQ + m]
    float* Vs = Ps + BN * SQ;       // [BN][DD]  : Vs[n*DD + d]

    const int tid = threadIdx.x;
    const int ty  = tid >> 3;       // 0..15 -> rows ty*4
    const int tx  = tid & 7;        // 0..7  -> cols tx*8
    const int b   = blockIdx.y;
    const int q0  = blockIdx.x * BM;

    const float* Q = g_q + (size_t)b * T_DIM * DD;
    const float* K = g_k + (size_t)b * T_DIM * DD;
    const float* V = g_v + (size_t)b * T_DIM * DD;

    // Load Q tile transposed (8 float4 per thread)
    #pragma unroll
    for (int i = 0; i < 8; i++) {
        int f   = tid + 128 * i;
        int row = f >> 4;           // 0..63
        int d0  = (f & 15) << 2;    // 0..60
        float4 v = *reinterpret_cast<const float4*>(&Q[(size_t)(q0 + row) * DD + d0]);
        Qs[(d0 + 0) * SQ + row] = v.x;
        Qs[(d0 + 1) * SQ + row] = v.y;
        Qs[(d0 + 2) * SQ + row] = v.z;
        Qs[(d0 + 3) * SQ + row] = v.w;
    }

    float acc[4][8];
    float rmax[4], rsum[4];
    #pragma unroll
    for (int i = 0; i < 4; i++) {
        rmax[i] = -1e30f;
        rsum[i] = 0.f;
        #pragma unroll
        for (int j = 0; j < 8; j++) acc[i][j] = 0.f;
    }

    for (int n0 = 0; n0 < T_DIM; n0 += BN) {
        __syncthreads();  // prior-iter readers of Ks/Vs done (also orders Qs on iter 0)

        // Load K tile transposed + V tile natural
        #pragma unroll
        for (int i = 0; i < 8; i++) {
            int f   = tid + 128 * i;
            int row = f >> 4;
            int d0  = (f & 15) << 2;
            float4 kv = *reinterpret_cast<const float4*>(&K[(size_t)(n0 + row) * DD + d0]);
            Ks[(d0 + 0) * SQ + row] = kv.x;
            Ks[(d0 + 1) * SQ + row] = kv.y;
            Ks[(d0 + 2) * SQ + row] = kv.z;
            Ks[(d0 + 3) * SQ + row] = kv.w;
            float4 vv = *reinterpret_cast<const float4*>(&V[(size_t)(n0 + row) * DD + d0]);
            *reinterpret_cast<float4*>(&Vs[row * DD + d0]) = vv;
        }
        __syncthreads();

        // S = Q @ K^T  (64x64x64), thread tile 4x8
        float s[4][8];
        #pragma unroll
        for (int i = 0; i < 4; i++)
            #pragma unroll
            for (int j = 0; j < 8; j++) s[i][j] = 0.f;

        #pragma unroll 8
        for (int d = 0; d < DD; d++) {
            float4 qa = *reinterpret_cast<const float4*>(&Qs[d * SQ + ty * 4]);
            float4 k0v = *reinterpret_cast<const float4*>(&Ks[d * SQ + tx * 8]);
            float4 k1v = *reinterpret_cast<const float4*>(&Ks[d * SQ + tx * 8 + 4]);
            float qq[4] = {qa.x, qa.y, qa.z, qa.w};
            float kk[8] = {k0v.x, k0v.y, k0v.z, k0v.w, k1v.x, k1v.y, k1v.z, k1v.w};
            #pragma unroll
            for (int i = 0; i < 4; i++)
                #pragma unroll
                for (int j = 0; j < 8; j++)
                    s[i][j] = fmaf(qq[i], kk[j], s[i][j]);
        }

        // Online softmax: row reductions across the 8 tx-lanes (width-8 shfl)
        #pragma unroll
        for (int i = 0; i < 4; i++) {
            float m = s[i][0];
            #pragma unroll
            for (int j = 1; j < 8; j++) m = fmaxf(m, s[i][j]);
            #pragma unroll
            for (int o = 1; o < 8; o <<= 1)
                m = fmaxf(m, __shfl_xor_sync(0xffffffffu, m, o, 8));

            float nm   = fmaxf(rmax[i], m);
            float corr = __expf(rmax[i] - nm);
            rmax[i] = nm;

            float ts = 0.f;
            #pragma unroll
            for (int j = 0; j < 8; j++) {
                float p = __expf(s[i][j] - nm);
                s[i][j] = p;
                ts += p;
            }
            #pragma unroll
            for (int o = 1; o < 8; o <<= 1)
                ts += __shfl_xor_sync(0xffffffffu, ts, o, 8);

            rsum[i] = rsum[i] * corr + ts;
            #pragma unroll
            for (int j = 0; j < 8; j++) acc[i][j] *= corr;
        }

        // Write P transposed: Ps[n][m]
        #pragma unroll
        for (int j = 0; j < 8; j++) {
            float4 pv = make_float4(s[0][j], s[1][j], s[2][j], s[3][j]);
            *reinterpret_cast<float4*>(&Ps[(tx * 8 + j) * SQ + ty * 4]) = pv;
        }
        __syncthreads();

        // O += P @ V  (64x64x64)
        #pragma unroll 8
        for (int n = 0; n < BN; n++) {
            float4 pa = *reinterpret_cast<const float4*>(&Ps[n * SQ + ty * 4]);
            float4 v0 = *reinterpret_cast<const float4*>(&Vs[n * DD + tx * 8]);
            float4 v1 = *reinterpret_cast<const float4*>(&Vs[n * DD + tx * 8 + 4]);
            float pp[4] = {pa.x, pa.y, pa.z, pa.w};
            float vv[8] = {v0.x, v0.y, v0.z, v0.w, v1.x, v1.y, v1.z, v1.w};
            #pragma unroll
            for (int i = 0; i < 4; i++)
                #pragma unroll
                for (int j = 0; j < 8; j++)
                    acc[i][j] = fmaf(pp[i], vv[j], acc[i][j]);
        }
    }

    // Epilogue: /rowsum, * 1/sqrt(D) = 0.125
    #pragma unroll
    for (int i = 0; i < 4; i++) {
        float sc = 0.125f / rsum[i];
        int m = q0 + ty * 4 + i;
        float4 o0 = make_float4(acc[i][0] * sc, acc[i][1] * sc,
                                acc[i][2] * sc, acc[i][3] * sc);
        float4 o1 = make_float4(acc[i][4] * sc, acc[i][5] * sc,
                                acc[i][6] * sc, acc[i][7] * sc);
        size_t base = ((size_t)b * T_DIM + m) * DD + tx * 8;
        *reinterpret_cast<float4*>(&out[base])     = o0;
        *reinterpret_cast<float4*>(&out[base + 4]) = o1;
    }
}

// ---------------------------------------------------------------------------
extern "C" void kernel_launch(void* const* d_in, const int* in_sizes, int n_in,
                              void* d_out, int out_size)
{
    const float* x  = (const float*)d_in[0];
    const float* Wq = (const float*)d_in[1];
    const float* Wk = (const float*)d_in[2];
    const float* Wv = (const float*)d_in[3];
    float* out = (float*)d_out;

    dim3 g1(M_ROWS / 128, 3);
    qkv_kernel<<<g1, 256>>>(x, Wq, Wk, Wv);

    const size_t smem = (size_t)(3 * 64 * 68 + 64 * 64) * sizeof(float);  // 68608 B
    cudaFuncSetAttribute(attn_kernel,
                         cudaFuncAttributeMaxDynamicSharedMemorySize, (int)smem);
    dim3 g2(T_DIM / 64, B_DIM);
    attn_kernel<<<g2, 128, smem>>>(out);
}

// round 2
// speedup vs baseline: 1.5898x; 1.5898x over previous
#include <cuda_runtime.h>

#define E_DIM 1024
#define D_DIM 64
#define B_DIM 4
#define T_DIM 4096
#define M_ROWS (B_DIM * T_DIM)   // 16384

typedef unsigned long long ull;

// Scratch for Q, K, V: [B*T, D] fp32 each. Device globals (no allocs).
__device__ float g_q[M_ROWS * D_DIM];
__device__ float g_k[M_ROWS * D_DIM];
__device__ float g_v[M_ROWS * D_DIM];

// ---------------- packed f32x2 helpers ----------------
__device__ __forceinline__ void ffma2(ull& d, ull a, ull b) {
    asm("fma.rn.f32x2 %0, %1, %2, %0;" : "+l"(d) : "l"(a), "l"(b));
}
__device__ __forceinline__ ull mul2(ull a, ull b) {
    ull r; asm("mul.rn.f32x2 %0, %1, %2;" : "=l"(r) : "l"(a), "l"(b)); return r;
}
__device__ __forceinline__ ull dup2(float x) {
    ull r; asm("mov.b64 %0, {%1, %1};" : "=l"(r) : "f"(x)); return r;
}
__device__ __forceinline__ ull pack2(float lo, float hi) {
    ull r; asm("mov.b64 %0, {%1, %2};" : "=l"(r) : "f"(lo), "f"(hi)); return r;
}
__device__ __forceinline__ void unpack2(ull v, float& lo, float& hi) {
    asm("mov.b64 {%0, %1}, %2;" : "=f"(lo), "=f"(hi) : "l"(v));
}
__device__ __forceinline__ void cp_async16(unsigned smem_addr, const void* gptr) {
    asm volatile("cp.async.ca.shared.global [%0], [%1], 16;" :: "r"(smem_addr), "l"(gptr));
}
__device__ __forceinline__ void cp_commit() {
    asm volatile("cp.async.commit_group;");
}
__device__ __forceinline__ void cp_wait0() {
    asm volatile("cp.async.wait_group 0;");
}

// ---------------------------------------------------------------------------
// Kernel 1: QKV projection.  C[m, d] = sum_e x[m, e] * W[e, d]
// Block tile 128x64, BK=32, 256 threads. Per-thread 8(m) x 4(n), packed pairs
// along m via fma.rn.f32x2. A tile stored transposed [k][m] with XOR swizzle.
// ---------------------------------------------------------------------------
__global__ __launch_bounds__(256)
void qkv_kernel(const float* __restrict__ x,
                const float* __restrict__ Wq,
                const float* __restrict__ Wk,
                const float* __restrict__ Wv)
{
    constexpr int BM = 128, BK = 32, BN = 64;
    __shared__ float As[BK * BM];   // transposed [k][m], swizzled
    __shared__ float Bs[BK * BN];   // natural [k][n]

    const int tid = threadIdx.x;
    const int ty  = tid >> 4;        // 0..15 -> rows ty*8 .. +7
    const int tx  = tid & 15;        // 0..15 -> cols tx*4 .. +3
    const int ty2 = ty << 1;
    const int m0  = blockIdx.x * BM;

    const float* W;
    float* C;
    if (blockIdx.y == 0)      { W = Wq; C = g_q; }
    else if (blockIdx.y == 1) { W = Wk; C = g_k; }
    else                      { W = Wv; C = g_v; }

    ull acc[4][4];
    #pragma unroll
    for (int p = 0; p < 4; p++)
        #pragma unroll
        for (int j = 0; j < 4; j++) acc[p][j] = 0ULL;

    // prefetch first tiles into regs
    float4 xr[4], wr[2];
    #pragma unroll
    for (int i = 0; i < 4; i++) {
        int f = tid + 256 * i;                 // 0..1023
        int m = f >> 3;                        // 0..127
        int kc = (f & 7) << 2;                 // 0..28
        xr[i] = *reinterpret_cast<const float4*>(&x[(size_t)(m0 + m) * E_DIM + kc]);
    }
    #pragma unroll
    for (int i = 0; i < 2; i++) {
        int f = tid + 256 * i;                 // 0..511
        int r = f >> 4;                        // 0..31
        int c4 = (f & 15) << 2;                // 0..60
        wr[i] = *reinterpret_cast<const float4*>(&W[(size_t)r * BN + c4]);
    }

    for (int k0 = 0; k0 < E_DIM; k0 += BK) {
        __syncthreads();
        // store A transposed + swizzled: phys = k*128 + ((m>>2)^((k>>2)&7))*4 + (m&3)
        #pragma unroll
        for (int i = 0; i < 4; i++) {
            int f = tid + 256 * i;
            int m = f >> 3;
            int kc = (f & 7) << 2;
            int slot = ((m >> 2) ^ (f & 7)) << 2;   // (kc+c)>>2 = f&7 for c<4
            int ml = m & 3;
            As[(kc + 0) * BM + slot + ml] = xr[i].x;
            As[(kc + 1) * BM + slot + ml] = xr[i].y;
            As[(kc + 2) * BM + slot + ml] = xr[i].z;
            As[(kc + 3) * BM + slot + ml] = xr[i].w;
        }
        #pragma unroll
        for (int i = 0; i < 2; i++) {
            int f = tid + 256 * i;
            int r = f >> 4;
            int c4 = (f & 15) << 2;
            *reinterpret_cast<float4*>(&Bs[r * BN + c4]) = wr[i];
        }
        // prefetch next tile
        if (k0 + BK < E_DIM) {
            #pragma unroll
            for (int i = 0; i < 4; i++) {
                int f = tid + 256 * i;
                int m = f >> 3;
                int kc = (f & 7) << 2;
                xr[i] = *reinterpret_cast<const float4*>(
                    &x[(size_t)(m0 + m) * E_DIM + k0 + BK + kc]);
            }
            #pragma unroll
            for (int i = 0; i < 2; i++) {
                int f = tid + 256 * i;
                int r = f >> 4;
                int c4 = (f & 15) << 2;
                wr[i] = *reinterpret_cast<const float4*>(
                    &W[(size_t)(k0 + BK + r) * BN + c4]);
            }
        }
        __syncthreads();

        #pragma unroll 2
        for (int k4 = 0; k4 < BK / 4; k4++) {
            const int g = k4 & 7;
            const int sa0 = ((ty2 + 0) ^ g) << 2;
            const int sa1 = ((ty2 + 1) ^ g) << 2;
            #pragma unroll
            for (int kk = 0; kk < 4; kk++) {
                const int k = (k4 << 2) + kk;
                const float* arow = As + k * BM;
                ulonglong2 a01 = *reinterpret_cast<const ulonglong2*>(arow + sa0);
                ulonglong2 a23 = *reinterpret_cast<const ulonglong2*>(arow + sa1);
                float4 bv = *reinterpret_cast<const float4*>(&Bs[k * BN + (tx << 2)]);
                ull b0 = dup2(bv.x), b1 = dup2(bv.y), b2 = dup2(bv.z), b3 = dup2(bv.w);
                ull ap[4] = {a01.x, a01.y, a23.x, a23.y};
                #pragma unroll
                for (int p = 0; p < 4; p++) {
                    ffma2(acc[p][0], ap[p], b0);
                    ffma2(acc[p][1], ap[p], b1);
                    ffma2(acc[p][2], ap[p], b2);
                    ffma2(acc[p][3], ap[p], b3);
                }
            }
        }
    }

    // epilogue
    #pragma unroll
    for (int p = 0; p < 4; p++) {
        float lo[4], hi[4];
        #pragma unroll
        for (int j = 0; j < 4; j++) unpack2(acc[p][j], lo[j], hi[j]);
        size_t r0 = (size_t)(m0 + ty * 8 + 2 * p) * D_DIM + (tx << 2);
        *reinterpret_cast<float4*>(&C[r0])         = make_float4(lo[0], lo[1], lo[2], lo[3]);
        *reinterpret_cast<float4*>(&C[r0 + D_DIM]) = make_float4(hi[0], hi[1], hi[2], hi[3]);
    }
}

// ---------------------------------------------------------------------------
// Kernel 2: fused flash attention. BM=BN=D=64, 128 threads.
// ty = tid>>4 (0..7): rows ty*8..+7 (4 packed pairs). tx = tid&15: cols tx*4..+3.
// Qs/Ks transposed [d][m] swizzled: phys = d*64 + ((m>>2)^((d>>2)&15))*4 + (m&3)
// Ps transposed [n][m] same swizzle. Vs natural, double-buffered via cp.async.
// K prefetched to regs one tile ahead.
// ---------------------------------------------------------------------------
__global__ __launch_bounds__(128)
void attn_kernel(float* __restrict__ out)
{
    constexpr int DD = 64, BN = 64;
    constexpr int NT = T_DIM / BN;   // 64 tiles

    extern __shared__ float sm[];
    float* Qs  = sm;                 // 4096
    float* Ks  = sm + 4096;          // 4096
    float* Ps  = sm + 8192;          // 4096
    float* Vs0 = sm + 12288;         // 4096
    float* Vs1 = sm + 16384;         // 4096

    const int tid = threadIdx.x;
    const int ty  = tid >> 4;        // 0..7
    const int tx  = tid & 15;        // 0..15
    const int ty2 = ty << 1;
    const int b   = blockIdx.y;
    const int q0  = blockIdx.x * 64;

    const float* Q = g_q + (size_t)b * T_DIM * DD;
    const float* K = g_k + (size_t)b * T_DIM * DD;
    const float* V = g_v + (size_t)b * T_DIM * DD;

    // loader geometry (per thread, 8 float4)
    int lrow[8], ld0[8], lslot[8];
    #pragma unroll
    for (int i = 0; i < 8; i++) {
        int f   = tid + 128 * i;
        lrow[i] = f >> 4;                          // 0..63
        ld0[i]  = (f & 15) << 2;                   // 0..60
        lslot[i] = (((f >> 4) >> 2) ^ (f & 15)) << 2;  // ((row>>2) ^ (d0>>2))*4
    }

    // ---- prologue: Q load+transpose, K prefetch, V cp.async tile 0 ----
    #pragma unroll
    for (int i = 0; i < 8; i++) {
        float4 v = *reinterpret_cast<const float4*>(&Q[(size_t)(q0 + lrow[i]) * DD + ld0[i]]);
        int ml = lrow[i] & 3;
        Qs[(ld0[i] + 0) * DD + lslot[i] + ml] = v.x;
        Qs[(ld0[i] + 1) * DD + lslot[i] + ml] = v.y;
        Qs[(ld0[i] + 2) * DD + lslot[i] + ml] = v.z;
        Qs[(ld0[i] + 3) * DD + lslot[i] + ml] = v.w;
    }
    float4 kr[8];
    #pragma unroll
    for (int i = 0; i < 8; i++)
        kr[i] = *reinterpret_cast<const float4*>(&K[(size_t)lrow[i] * DD + ld0[i]]);
    {
        unsigned vbase = (unsigned)__cvta_generic_to_shared(Vs0);
        #pragma unroll
        for (int i = 0; i < 8; i++)
            cp_async16(vbase + (unsigned)((lrow[i] * DD + ld0[i]) << 2),
                       &V[(size_t)lrow[i] * DD + ld0[i]]);
        cp_commit();
    }

    ull acc[4][4];
    float rmax[8], rsum[8];
    #pragma unroll
    for (int p = 0; p < 4; p++)
        #pragma unroll
        for (int j = 0; j < 4; j++) acc[p][j] = 0ULL;
    #pragma unroll
    for (int i = 0; i < 8; i++) { rmax[i] = -1e30f; rsum[i] = 0.f; }

    for (int t = 0; t < NT; t++) {
        float* Vcur = (t & 1) ? Vs1 : Vs0;
        float* Vnxt = (t & 1) ? Vs0 : Vs1;

        cp_wait0();
        __syncthreads();   // prev compute done; V(t) visible

        // store K(t) transposed + swizzled from regs
        #pragma unroll
        for (int i = 0; i < 8; i++) {
            int ml = lrow[i] & 3;
            Ks[(ld0[i] + 0) * DD + lslot[i] + ml] = kr[i].x;
            Ks[(ld0[i] + 1) * DD + lslot[i] + ml] = kr[i].y;
            Ks[(ld0[i] + 2) * DD + lslot[i] + ml] = kr[i].z;
            Ks[(ld0[i] + 3) * DD + lslot[i] + ml] = kr[i].w;
        }
        // prefetch next K / V
        if (t + 1 < NT) {
            const int n1 = (t + 1) * BN;
            #pragma unroll
            for (int i = 0; i < 8; i++)
                kr[i] = *reinterpret_cast<const float4*>(
                    &K[(size_t)(n1 + lrow[i]) * DD + ld0[i]]);
            unsigned vbase = (unsigned)__cvta_generic_to_shared(Vnxt);
            #pragma unroll
            for (int i = 0; i < 8; i++)
                cp_async16(vbase + (unsigned)((lrow[i] * DD + ld0[i]) << 2),
                           &V[(size_t)(n1 + lrow[i]) * DD + ld0[i]]);
            cp_commit();
        }
        __syncthreads();   // Ks visible

        // ---- S = Q @ K^T : packed pairs along m ----
        ull s2[4][4];
        #pragma unroll
        for (int p = 0; p < 4; p++)
            #pragma unroll
            for (int j = 0; j < 4; j++) s2[p][j] = 0ULL;

        #pragma unroll 2
        for (int d4 = 0; d4 < 16; d4++) {
            const int sq0 = ((ty2 + 0) ^ d4) << 2;
            const int sq1 = ((ty2 + 1) ^ d4) << 2;
            const int sk  = (tx ^ d4) << 2;
            #pragma unroll
            for (int dd = 0; dd < 4; dd++) {
                const float* row = Qs + ((d4 << 2) + dd) * DD;
                const float* krow = Ks + ((d4 << 2) + dd) * DD;
                ulonglong2 qa = *reinterpret_cast<const ulonglong2*>(row + sq0);
                ulonglong2 qb = *reinterpret_cast<const ulonglong2*>(row + sq1);
                float4 kv = *reinterpret_cast<const float4*>(krow + sk);
                ull k0 = dup2(kv.x), k1 = dup2(kv.y), k2 = dup2(kv.z), k3 = dup2(kv.w);
                ull qp[4] = {qa.x, qa.y, qb.x, qb.y};
                #pragma unroll
                for (int p = 0; p < 4; p++) {
                    ffma2(s2[p][0], qp[p], k0);
                    ffma2(s2[p][1], qp[p], k1);
                    ffma2(s2[p][2], qp[p], k2);
                    ffma2(s2[p][3], qp[p], k3);
                }
            }
        }

        // ---- online softmax (unscaled) ----
        float s[8][4];
        #pragma unroll
        for (int p = 0; p < 4; p++)
            #pragma unroll
            for (int j = 0; j < 4; j++) unpack2(s2[p][j], s[2 * p][j], s[2 * p + 1][j]);

        float corr[8];
        #pragma unroll
        for (int m = 0; m < 8; m++) {
            float mx = fmaxf(fmaxf(s[m][0], s[m][1]), fmaxf(s[m][2], s[m][3]));
            #pragma unroll
            for (int o = 1; o < 16; o <<= 1)
                mx = fmaxf(mx, __shfl_xor_sync(0xffffffffu, mx, o, 16));
            float nm = fmaxf(rmax[m], mx);
            corr[m] = __expf(rmax[m] - nm);
            rmax[m] = nm;
            float ts = 0.f;
            #pragma unroll
            for (int j = 0; j < 4; j++) {
                float p = __expf(s[m][j] - nm);
                s[m][j] = p;
                ts += p;
            }
            #pragma unroll
            for (int o = 1; o < 16; o <<= 1)
                ts += __shfl_xor_sync(0xffffffffu, ts, o, 16);
            rsum[m] = rsum[m] * corr[m] + ts;
        }
        #pragma unroll
        for (int p = 0; p < 4; p++) {
            ull c2 = pack2(corr[2 * p], corr[2 * p + 1]);
            #pragma unroll
            for (int j = 0; j < 4; j++) acc[p][j] = mul2(acc[p][j], c2);
        }

        // ---- store P transposed: Ps[n][m], slot = (m>>2) ^ (n>>2) ----
        #pragma unroll
        for (int h = 0; h < 2; h++) {
            const int slot = ((ty2 + h) ^ tx) << 2;
            #pragma unroll
            for (int j = 0; j < 4; j++) {
                float4 pv = make_float4(s[4 * h + 0][j], s[4 * h + 1][j],
                                        s[4 * h + 2][j], s[4 * h + 3][j]);
                *reinterpret_cast<float4*>(&Ps[((tx << 2) + j) * DD + slot]) = pv;
            }
        }
        __syncthreads();   // Ps visible

        // ---- O += P @ V ----
        #pragma unroll 2
        for (int n4 = 0; n4 < 16; n4++) {
            const int sp0 = ((ty2 + 0) ^ n4) << 2;
            const int sp1 = ((ty2 + 1) ^ n4) << 2;
            #pragma unroll
            for (int nn = 0; nn < 4; nn++) {
                const int n = (n4 << 2) + nn;
                const float* prow = Ps + n * DD;
                ulonglong2 pa = *reinterpret_cast<const ulonglong2*>(prow + sp0);
                ulonglong2 pb = *reinterpret_cast<const ulonglong2*>(prow + sp1);
                float4 vv = *reinterpret_cast<const float4*>(Vcur + n * DD + (tx << 2));
                ull v0 = dup2(vv.x), v1 = dup2(vv.y), v2 = dup2(vv.z), v3 = dup2(vv.w);
                ull pp[4] = {pa.x, pa.y, pb.x, pb.y};
                #pragma unroll
                for (int p = 0; p < 4; p++) {
                    ffma2(acc[p][0], pp[p], v0);
                    ffma2(acc[p][1], pp[p], v1);
                    ffma2(acc[p][2], pp[p], v2);
                    ffma2(acc[p][3], pp[p], v3);
                }
            }
        }
    }

    // ---- epilogue: /rowsum, *1/sqrt(D)=0.125 ----
    #pragma unroll
    for (int p = 0; p < 4; p++) {
        float lo[4], hi[4];
        #pragma unroll
        for (int j = 0; j < 4; j++) unpack2(acc[p][j], lo[j], hi[j]);
        float sc0 = 0.125f / rsum[2 * p];
        float sc1 = 0.125f / rsum[2 * p + 1];
        int m = q0 + ty * 8 + 2 * p;
        size_t base = ((size_t)b * T_DIM + m) * DD + (tx << 2);
        *reinterpret_cast<float4*>(&out[base]) =
            make_float4(lo[0] * sc0, lo[1] * sc0, lo[2] * sc0, lo[3] * sc0);
        *reinterpret_cast<float4*>(&out[base + DD]) =
            make_float4(hi[0] * sc1, hi[1] * sc1, hi[2] * sc1, hi[3] * sc1);
    }
}

// ---------------------------------------------------------------------------
extern "C" void kernel_launch(void* const* d_in, const int* in_sizes, int n_in,
                              void* d_out, int out_size)
{
    const float* x  = (const float*)d_in[0];
    const float* Wq = (const float*)d_in[1];
    const float* Wk = (const float*)d_in[2];
    const float* Wv = (const float*)d_in[3];
    float* out = (float*)d_out;

    dim3 g1(M_ROWS / 128, 3);
    qkv_kernel<<<g1, 256>>>(x, Wq, Wk, Wv);

    const size_t smem = 20480 * sizeof(float);   // 81920 B
    cudaFuncSetAttribute(attn_kernel,
                         cudaFuncAttributeMaxDynamicSharedMemorySize, (int)smem);
    dim3 g2(T_DIM / 64, B_DIM);
    attn_kernel<<<g2, 128, smem>>>(out);
}